// round 11
// baseline (speedup 1.0000x reference)
#include <cuda_runtime.h>
#include <cuda_bf16.h>
#include <cuda_fp16.h>
#include <stdint.h>
#include <cstdint>
#include <math.h>

#define NN 50000
#define EE 400000
#define BG 16
#define HD 256      // fs / fd columns
#define NBLK ((NN + 256) / 256)   // 196 scan blocks

// 16B-chunk XOR swizzle on 128B rows (64 halves): conflict-free ldmatrix
#define SWZ(r, c8) (((r) << 7) | ((((c8) ^ ((r) & 7))) << 4))
#define ATILE 16384                 // one 128x64-half tile, bytes
#define SMEM_A (2 * ATILE)          // 32 KB (Ahi, Alo)
#define SMEM_B (2 * ATILE)          // 32 KB per buffer (Whi, Wlo)
#define SMEM_TOT (SMEM_A + 2 * SMEM_B)   // 96 KB

// ---------------- device scratch (static globals: no allocation) -------------
__device__ __align__(16) float g_hfin[NN * 64];
__device__ __align__(16) __half g_fsh[NN * HD];    // 25.6 MB
__device__ __align__(16) __half g_fdh[NN * HD];    // 25.6 MB
__device__ __align__(16) __half g_gc[NN * 512];    // 51.2 MB  h0@Wbot + bias
__device__ __align__(16) __nv_bfloat16 g_Ahi[NN * 64];
__device__ __align__(16) __nv_bfloat16 g_Alo[NN * 64];
__device__ __align__(16) __nv_bfloat16 g_A0hi[NN * 64];
__device__ __align__(16) __nv_bfloat16 g_A0lo[NN * 64];
__device__ __align__(16) __nv_bfloat16 g_Wth[512 * 64];  // Wtop hi  [n][k]
__device__ __align__(16) __nv_bfloat16 g_Wtl[512 * 64];  // Wtop lo
__device__ __align__(16) __nv_bfloat16 g_Wbh[512 * 64];  // Wbot hi
__device__ __align__(16) __nv_bfloat16 g_Wbl[512 * 64];  // Wbot lo
__device__ __align__(16) __nv_bfloat16 g_Wch[512 * 64];  // (Wtop+Wbot) hi (layer 0)
__device__ __align__(16) __nv_bfloat16 g_Wcl[512 * 64];  // (Wtop+Wbot) lo
__device__ __align__(16) float g_bias2[512];
__device__ int   g_rowoff[NN + 1];
__device__ int   g_cursor[NN];
__device__ int   g_esrc[EE];
__device__ int   g_bsum[NBLK];
__device__ float g_hg[BG * 64];

// ---------------- asm helpers -------------------------------------------------
__device__ __forceinline__ uint32_t s2u(const void* p) {
    uint32_t a;
    asm("{ .reg .u64 t; cvta.to.shared.u64 t, %1; cvt.u32.u64 %0, t; }"
        : "=r"(a) : "l"(p));
    return a;
}
__device__ __forceinline__ void cpa16(uint32_t dst, const void* src) {
    asm volatile("cp.async.cg.shared.global [%0], [%1], 16;" :: "r"(dst), "l"(src));
}
#define CPA_COMMIT() asm volatile("cp.async.commit_group;" ::: "memory")
#define CPA_WAIT0()  asm volatile("cp.async.wait_group 0;" ::: "memory")

__device__ __forceinline__ void ldsm_x4(uint32_t& r0, uint32_t& r1, uint32_t& r2,
                                        uint32_t& r3, uint32_t addr) {
    asm volatile("ldmatrix.sync.aligned.m8n8.x4.shared.b16 {%0,%1,%2,%3}, [%4];"
                 : "=r"(r0), "=r"(r1), "=r"(r2), "=r"(r3) : "r"(addr));
}
__device__ __forceinline__ void mma16816(float* d, const uint32_t* a,
                                         uint32_t b0, uint32_t b1) {
    asm volatile(
        "mma.sync.aligned.m16n8k16.row.col.f32.bf16.bf16.f32 "
        "{%0,%1,%2,%3}, {%4,%5,%6,%7}, {%8,%9}, {%0,%1,%2,%3};"
        : "+f"(d[0]), "+f"(d[1]), "+f"(d[2]), "+f"(d[3])
        : "r"(a[0]), "r"(a[1]), "r"(a[2]), "r"(a[3]), "r"(b0), "r"(b1));
}

__device__ __forceinline__ void unp8(const uint4& u, float* f) {
    const __half2* hp = (const __half2*)&u;
    float2 a = __half22float2(hp[0]), b = __half22float2(hp[1]);
    float2 c = __half22float2(hp[2]), d = __half22float2(hp[3]);
    f[0] = a.x; f[1] = a.y; f[2] = b.x; f[3] = b.y;
    f[4] = c.x; f[5] = c.y; f[6] = d.x; f[7] = d.y;
}

// ---------------- fused setup kernels -----------------------------------------
__global__ void k_cvtW(const float* __restrict__ Ws, const float* __restrict__ Wd,
                       const float* __restrict__ bs, const float* __restrict__ bd) {
    int idx = blockIdx.x * blockDim.x + threadIdx.x;
    if (idx <= NN) g_rowoff[idx] = 0;
    if (idx < BG * 64) g_hg[idx] = 0.f;
    if (idx >= 512 * 64) return;
    int n = idx >> 6, k = idx & 63;
    float wt = (n < 256) ? Ws[k * 256 + n] : Wd[k * 256 + (n - 256)];
    float wb = (n < 256) ? Ws[(k + 64) * 256 + n] : Wd[(k + 64) * 256 + (n - 256)];
    float wc = wt + wb;
    __nv_bfloat16 th = __float2bfloat16(wt);
    __nv_bfloat16 bh = __float2bfloat16(wb);
    __nv_bfloat16 ch = __float2bfloat16(wc);
    g_Wth[idx] = th;  g_Wtl[idx] = __float2bfloat16(wt - __bfloat162float(th));
    g_Wbh[idx] = bh;  g_Wbl[idx] = __float2bfloat16(wb - __bfloat162float(bh));
    g_Wch[idx] = ch;  g_Wcl[idx] = __float2bfloat16(wc - __bfloat162float(ch));
    if (idx < 512) g_bias2[idx] = (idx < 256) ? bs[idx] : bd[idx - 256];
}

__global__ void k_h0(const float* __restrict__ feat, const float* __restrict__ W_in,
                     const float* __restrict__ b_in, const int* __restrict__ dst) {
    int idx = blockIdx.x * blockDim.x + threadIdx.x;
    if (idx >= NN * 64) return;
    if (idx < EE) atomicAdd(&g_rowoff[dst[idx] + 1], 1);
    int i = idx >> 6, d = idx & 63;
    const float4* f4 = (const float4*)(feat + i * 16);
    float4 f0 = f4[0], f1 = f4[1], f2 = f4[2], f3 = f4[3];
    float s = b_in[d];
    s = fmaf(f0.x, W_in[0 * 64 + d], s);  s = fmaf(f0.y, W_in[1 * 64 + d], s);
    s = fmaf(f0.z, W_in[2 * 64 + d], s);  s = fmaf(f0.w, W_in[3 * 64 + d], s);
    s = fmaf(f1.x, W_in[4 * 64 + d], s);  s = fmaf(f1.y, W_in[5 * 64 + d], s);
    s = fmaf(f1.z, W_in[6 * 64 + d], s);  s = fmaf(f1.w, W_in[7 * 64 + d], s);
    s = fmaf(f2.x, W_in[8 * 64 + d], s);  s = fmaf(f2.y, W_in[9 * 64 + d], s);
    s = fmaf(f2.z, W_in[10 * 64 + d], s); s = fmaf(f2.w, W_in[11 * 64 + d], s);
    s = fmaf(f3.x, W_in[12 * 64 + d], s); s = fmaf(f3.y, W_in[13 * 64 + d], s);
    s = fmaf(f3.z, W_in[14 * 64 + d], s); s = fmaf(f3.w, W_in[15 * 64 + d], s);
    __nv_bfloat16 hi = __float2bfloat16(s);
    g_A0hi[idx] = hi;
    g_A0lo[idx] = __float2bfloat16(s - __bfloat162float(hi));
}

// ---------------- parallel CSR scan -------------------------------------------
__global__ void k_scan1() {
    __shared__ int ws[8];
    int b = blockIdx.x, t = threadIdx.x;
    int lane = t & 31, w = t >> 5;
    int idx = b * 256 + t;
    int x = (idx <= NN) ? g_rowoff[idx] : 0;
#pragma unroll
    for (int off = 1; off < 32; off <<= 1) {
        int y = __shfl_up_sync(0xffffffffu, x, off);
        if (lane >= off) x += y;
    }
    if (lane == 31) ws[w] = x;
    __syncthreads();
    if (w == 0 && lane < 8) {
        int v = ws[lane];
#pragma unroll
        for (int off = 1; off < 8; off <<= 1) {
            int y = __shfl_up_sync(0x000000ffu, v, off, 8);
            if (lane >= off) v += y;
        }
        ws[lane] = v;
    }
    __syncthreads();
    int add = w ? ws[w - 1] : 0;
    x += add;
    if (idx <= NN) g_rowoff[idx] = x;
    if (t == 255) g_bsum[b] = x;
}

__global__ void k_scan3() {
    __shared__ int ws[8];
    int b = blockIdx.x, t = threadIdx.x;
    int lane = t & 31, w = t >> 5;
    int v = (t < b && t < NBLK) ? g_bsum[t] : 0;
#pragma unroll
    for (int off = 16; off > 0; off >>= 1)
        v += __shfl_xor_sync(0xffffffffu, v, off);
    if (lane == 0) ws[w] = v;
    __syncthreads();
    if (t == 0) {
        int s = 0;
#pragma unroll
        for (int i = 0; i < 8; i++) s += ws[i];
        ws[0] = s;
    }
    __syncthreads();
    int add = ws[0];
    int idx = b * 256 + t;
    if (idx <= NN) {
        int r = g_rowoff[idx] + add;
        g_rowoff[idx] = r;
        if (idx < NN) g_cursor[idx] = r;
    }
}

__global__ void k_scatter(const int* __restrict__ src, const int* __restrict__ dst) {
    int e = blockIdx.x * blockDim.x + threadIdx.x;
    if (e < EE) {
        int d = dst[e];
        int p = atomicAdd(&g_cursor[d], 1);
        g_esrc[p] = src[e];
    }
}

// ---------------- HMMA GEMM (persistent over N, cp.async double-buffered B) ----
// Uniform 3-term bf16-split group: acc += Ahi*WH + Ahi*WL + Alo*WH.
// mode 0: A=A0, W=Wbot -> g_gc (+bias)        [precompute, once]
// mode 1: A=A0, W=Wtop+Wbot -> fs/fd (+bias)  [layer 0]
// mode 2: A=A,  W=Wtop -> fs/fd (+g_gc)       [layers 1-3]
__device__ __forceinline__ void do_grp(uint32_t aH, uint32_t aL,
                                       uint32_t bH, uint32_t bL,
                                       float (&acc)[2][8][4],
                                       int wm, int wn, int a_lrow, int a_c8,
                                       int b_lrow, int b_c8) {
#pragma unroll
    for (int k16 = 0; k16 < 4; k16++) {
        int kc8 = k16 * 2;
        uint32_t afH[2][4], afL[2][4];
#pragma unroll
        for (int mt = 0; mt < 2; mt++) {
            int r = wm + mt * 16 + a_lrow;
            ldsm_x4(afH[mt][0], afH[mt][1], afH[mt][2], afH[mt][3],
                    aH + SWZ(r, kc8 + a_c8));
            ldsm_x4(afL[mt][0], afL[mt][1], afL[mt][2], afL[mt][3],
                    aL + SWZ(r, kc8 + a_c8));
        }
        uint32_t bfH[4][4], bfL[4][4];
#pragma unroll
        for (int p = 0; p < 4; p++) {
            int r = wn + p * 16 + b_lrow;
            ldsm_x4(bfH[p][0], bfH[p][1], bfH[p][2], bfH[p][3],
                    bH + SWZ(r, kc8 + b_c8));
            ldsm_x4(bfL[p][0], bfL[p][1], bfL[p][2], bfL[p][3],
                    bL + SWZ(r, kc8 + b_c8));
        }
#pragma unroll
        for (int mt = 0; mt < 2; mt++)
#pragma unroll
            for (int nt = 0; nt < 8; nt++) {
                uint32_t h0 = bfH[nt >> 1][(nt & 1) * 2], h1 = bfH[nt >> 1][(nt & 1) * 2 + 1];
                uint32_t l0 = bfL[nt >> 1][(nt & 1) * 2], l1 = bfL[nt >> 1][(nt & 1) * 2 + 1];
                mma16816(acc[mt][nt], afH[mt], h0, h1);
                mma16816(acc[mt][nt], afH[mt], l0, l1);
                mma16816(acc[mt][nt], afL[mt], h0, h1);
            }
    }
}

__global__ void __launch_bounds__(256, 1) k_mma(int mode) {
    extern __shared__ char sm[];
    const int tid = threadIdx.x;
    const int lane = tid & 31;
    const int wid = tid >> 5;
    const int wm = (wid >> 1) * 32;
    const int wn = (wid & 1) * 64;
    const int row0 = blockIdx.x * 128;

    const uint32_t uA = s2u(sm);
    const uint32_t uB = uA + SMEM_A;

    const __nv_bfloat16* aH = (mode == 2) ? g_Ahi : g_A0hi;
    const __nv_bfloat16* aL = (mode == 2) ? g_Alo : g_A0lo;
    const __nv_bfloat16* bH = (mode == 0) ? g_Wbh : (mode == 1) ? g_Wch : g_Wth;
    const __nv_bfloat16* bL = (mode == 0) ? g_Wbl : (mode == 1) ? g_Wcl : g_Wtl;
    const __nv_bfloat16* asrc[2] = {aH, aL};
    const __nv_bfloat16* bsrc[2] = {bH, bL};

    for (int a = 0; a < 2; a++) {
        const __nv_bfloat16* s = asrc[a];
        uint32_t base = uA + a * ATILE;
#pragma unroll
        for (int it = 0; it < 4; it++) {
            int idx = tid + 256 * it;
            int r = idx >> 3, c8 = idx & 7;
            int grow = row0 + r;
            if (grow < NN)
                cpa16(base + SWZ(r, c8), s + (size_t)grow * 64 + c8 * 8);
            else
                *(float4*)(sm + a * ATILE + SWZ(r, c8)) = make_float4(0.f, 0.f, 0.f, 0.f);
        }
    }
    for (int b = 0; b < 2; b++) {
        const __nv_bfloat16* s = bsrc[b];
        uint32_t base = uB + b * ATILE;
#pragma unroll
        for (int it = 0; it < 4; it++) {
            int idx = tid + 256 * it;
            int r = idx >> 3, c8 = idx & 7;
            cpa16(base + SWZ(r, c8), s + (size_t)r * 64 + c8 * 8);
        }
    }
    CPA_COMMIT();
    CPA_WAIT0();
    __syncthreads();

    const int a_lrow = lane & 15;
    const int a_c8 = lane >> 4;
    const int b_lrow = (lane & 7) + ((lane >> 4) << 3);
    const int b_c8 = (lane & 8) >> 3;

#pragma unroll
    for (int blk = 0; blk < 4; blk++) {
        const uint32_t bBuf = uB + (blk & 1) * SMEM_B;

        if (blk < 3) {
            uint32_t nBuf = uB + ((blk + 1) & 1) * SMEM_B;
            int nrow0 = (blk + 1) * 128;
            for (int b = 0; b < 2; b++) {
                const __nv_bfloat16* s = bsrc[b] + (size_t)nrow0 * 64;
                uint32_t base = nBuf + b * ATILE;
#pragma unroll
                for (int it = 0; it < 4; it++) {
                    int idx = tid + 256 * it;
                    int r = idx >> 3, c8 = idx & 7;
                    cpa16(base + SWZ(r, c8), s + (size_t)r * 64 + c8 * 8);
                }
            }
            CPA_COMMIT();
        }

        float acc[2][8][4];
#pragma unroll
        for (int mt = 0; mt < 2; mt++)
#pragma unroll
            for (int nt = 0; nt < 8; nt++)
#pragma unroll
                for (int j = 0; j < 4; j++) acc[mt][nt][j] = 0.f;

        do_grp(uA, uA + ATILE, bBuf, bBuf + ATILE,
               acc, wm, wn, a_lrow, a_c8, b_lrow, b_c8);

        // ---- epilogue ----
        {
            int col0 = blk * 128;
            if (mode == 0) {
                // write g_gc (all 512 cols), + bias
#pragma unroll
                for (int nt = 0; nt < 8; nt++) {
                    int gcol = col0 + wn + nt * 8 + (lane & 3) * 2;
                    float b0 = g_bias2[gcol], b1 = g_bias2[gcol + 1];
#pragma unroll
                    for (int mt = 0; mt < 2; mt++) {
                        int rr = row0 + wm + mt * 16 + (lane >> 2);
                        if (rr < NN)
                            *(__half2*)&g_gc[(size_t)rr * 512 + gcol] =
                                __floats2half2_rn(acc[mt][nt][0] + b0, acc[mt][nt][1] + b1);
                        if (rr + 8 < NN)
                            *(__half2*)&g_gc[(size_t)(rr + 8) * 512 + gcol] =
                                __floats2half2_rn(acc[mt][nt][2] + b0, acc[mt][nt][3] + b1);
                    }
                }
            } else {
                __half* Cb = (col0 < 256) ? g_fsh : g_fdh;
                const int cb0 = (col0 < 256) ? col0 : col0 - 256;
#pragma unroll
                for (int nt = 0; nt < 8; nt++) {
                    int gcol = col0 + wn + nt * 8 + (lane & 3) * 2;
                    float b0, b1;
                    if (mode == 1) { b0 = g_bias2[gcol]; b1 = g_bias2[gcol + 1]; }
                    int cc = cb0 + wn + nt * 8 + (lane & 3) * 2;
#pragma unroll
                    for (int mt = 0; mt < 2; mt++) {
                        int rr = row0 + wm + mt * 16 + (lane >> 2);
                        if (rr < NN) {
                            float a0 = acc[mt][nt][0], a1 = acc[mt][nt][1];
                            if (mode == 2) {
                                float2 g = __half22float2(*(const __half2*)&g_gc[(size_t)rr * 512 + gcol]);
                                a0 += g.x; a1 += g.y;
                            } else { a0 += b0; a1 += b1; }
                            *(__half2*)&Cb[(size_t)rr * HD + cc] = __floats2half2_rn(a0, a1);
                        }
                        if (rr + 8 < NN) {
                            float a2 = acc[mt][nt][2], a3 = acc[mt][nt][3];
                            if (mode == 2) {
                                float2 g = __half22float2(*(const __half2*)&g_gc[(size_t)(rr + 8) * 512 + gcol]);
                                a2 += g.x; a3 += g.y;
                            } else { a2 += b0; a3 += b1; }
                            *(__half2*)&Cb[(size_t)(rr + 8) * HD + cc] = __floats2half2_rn(a2, a3);
                        }
                    }
                }
            }
        }

        if (blk < 3) {
            CPA_WAIT0();
            __syncthreads();
        }
    }
}

// ---------------- edge aggregation: one warp per node, 4-edge batches ---------
__global__ void __launch_bounds__(256) k_agg(const float* __restrict__ attn, int last) {
    int gw = (blockIdx.x * blockDim.x + threadIdx.x) >> 5;
    int lane = threadIdx.x & 31;
    if (gw >= NN) return;

    int base = lane * 8;
    float fd[8], at[8];
    {
        uint4 u = *(const uint4*)(g_fdh + (size_t)gw * HD + base);
        unp8(u, fd);
        float4 atA = *(const float4*)(attn + base);
        float4 atB = *(const float4*)(attn + base + 4);
        at[0] = atA.x; at[1] = atA.y; at[2] = atA.z; at[3] = atA.w;
        at[4] = atB.x; at[5] = atB.y; at[6] = atB.z; at[7] = atB.w;
    }

    float m = -1e30f, denom = 0.f;
    float acc[8];
#pragma unroll
    for (int j = 0; j < 8; j++) acc[j] = 0.f;

    int e0 = g_rowoff[gw], e1 = g_rowoff[gw + 1];
    for (int e = e0; e < e1; e += 4) {
        int n = e1 - e;
        int s0 = g_esrc[e];
        int s1 = (n > 1) ? g_esrc[e + 1] : s0;
        int s2 = (n > 2) ? g_esrc[e + 2] : s0;
        int s3 = (n > 3) ? g_esrc[e + 3] : s0;
        uint4 u0 = *(const uint4*)(g_fsh + (size_t)s0 * HD + base);
        uint4 u1 = *(const uint4*)(g_fsh + (size_t)s1 * HD + base);
        uint4 u2 = *(const uint4*)(g_fsh + (size_t)s2 * HD + base);
        uint4 u3 = *(const uint4*)(g_fsh + (size_t)s3 * HD + base);

        float f0[8], f1[8], f2[8], f3[8];
        unp8(u0, f0); unp8(u1, f1); unp8(u2, f2); unp8(u3, f3);

        float p0 = 0.f, p1 = 0.f, p2 = 0.f, p3 = 0.f;
#pragma unroll
        for (int j = 0; j < 8; j++) {
            float v;
            v = f0[j] + fd[j]; v = (v > 0.f) ? v : 0.2f * v; p0 = fmaf(v, at[j], p0);
            v = f1[j] + fd[j]; v = (v > 0.f) ? v : 0.2f * v; p1 = fmaf(v, at[j], p1);
            v = f2[j] + fd[j]; v = (v > 0.f) ? v : 0.2f * v; p2 = fmaf(v, at[j], p2);
            v = f3[j] + fd[j]; v = (v > 0.f) ? v : 0.2f * v; p3 = fmaf(v, at[j], p3);
        }
#pragma unroll
        for (int off = 1; off < 8; off <<= 1) {
            p0 += __shfl_xor_sync(0xffffffffu, p0, off);
            p1 += __shfl_xor_sync(0xffffffffu, p1, off);
            p2 += __shfl_xor_sync(0xffffffffu, p2, off);
            p3 += __shfl_xor_sync(0xffffffffu, p3, off);
        }
        if (n < 2) p1 = -1e30f;
        if (n < 3) p2 = -1e30f;
        if (n < 4) p3 = -1e30f;

        float mb = fmaxf(fmaxf(p0, p1), fmaxf(p2, p3));
        float nm = fmaxf(m, mb);
        float sc = __expf(m - nm);
        float w0 = __expf(p0 - nm);
        float w1 = __expf(p1 - nm);
        float w2 = __expf(p2 - nm);
        float w3 = __expf(p3 - nm);
        m = nm;
        denom = fmaf(denom, sc, (w0 + w1) + (w2 + w3));
#pragma unroll
        for (int j = 0; j < 8; j++) {
            float s = fmaf(w0, f0[j], w1 * f1[j]);
            s = fmaf(w2, f2[j], s);
            s = fmaf(w3, f3[j], s);
            acc[j] = fmaf(acc[j], sc, s);
        }
    }

    float inv = (denom > 0.f) ? (1.f / denom) : 0.f;
    float t[8];
#pragma unroll
    for (int j = 0; j < 8; j++) t[j] = tanhf(acc[j] * inv);
#pragma unroll
    for (int j = 0; j < 8; j++) {
        t[j] += __shfl_xor_sync(0xffffffffu, t[j], 8);
        t[j] += __shfl_xor_sync(0xffffffffu, t[j], 16);
    }
    if (lane < 8) {
        size_t ofs = (size_t)gw * 64 + lane * 8;
        if (last) {
            float* hout = g_hfin + ofs;
#pragma unroll
            for (int j = 0; j < 8; j++) hout[j] = t[j];
        } else {
            __nv_bfloat16* ah = g_Ahi + ofs;
            __nv_bfloat16* al = g_Alo + ofs;
#pragma unroll
            for (int j = 0; j < 8; j++) {
                __nv_bfloat16 hi = __float2bfloat16(t[j]);
                ah[j] = hi;
                al[j] = __float2bfloat16(t[j] - __bfloat162float(hi));
            }
        }
    }
}

// ---------------- graph pooling + output head --------------------------------
__global__ void k_pool(const float* __restrict__ is_root, const int* __restrict__ gid) {
    __shared__ float sh[BG * 64];
    int t = threadIdx.x;
    for (int x = t; x < BG * 64; x += 256) sh[x] = 0.f;
    __syncthreads();
    for (int idx = blockIdx.x * 256 + t; idx < NN * 64; idx += gridDim.x * 256) {
        int i = idx >> 6, d = idx & 63;
        atomicAdd(&sh[(gid[i] << 6) | d], g_hfin[idx] * is_root[i]);
    }
    __syncthreads();
    for (int x = t; x < BG * 64; x += 256) atomicAdd(&g_hg[x], sh[x]);
}

__global__ void k_out(const float* __restrict__ W_out, const float* __restrict__ b_out,
                      float* __restrict__ out) {
    int t = threadIdx.x;
    if (t >= BG * 32) return;
    int b = t >> 5, j = t & 31;
    float s = b_out[j];
#pragma unroll
    for (int d = 0; d < 64; d++) s = fmaf(g_hg[b * 64 + d], W_out[d * 32 + j], s);
    out[t] = s;
}

// ---------------- launcher ----------------------------------------------------
extern "C" void kernel_launch(void* const* d_in, const int* in_sizes, int n_in,
                              void* d_out, int out_size) {
    const float* feat    = (const float*)d_in[0];
    const float* is_root = (const float*)d_in[1];
    const int*   src     = (const int*)  d_in[2];
    const int*   dst     = (const int*)  d_in[3];
    const int*   gid     = (const int*)  d_in[4];
    const float* W_in    = (const float*)d_in[5];
    const float* b_in    = (const float*)d_in[6];
    const float* W_src   = (const float*)d_in[7];
    const float* b_src   = (const float*)d_in[8];
    const float* W_dst   = (const float*)d_in[9];
    const float* b_dst   = (const float*)d_in[10];
    const float* attn    = (const float*)d_in[11];
    const float* W_out   = (const float*)d_in[12];
    const float* b_out   = (const float*)d_in[13];
    float* out = (float*)d_out;

    cudaFuncSetAttribute(k_mma, cudaFuncAttributeMaxDynamicSharedMemorySize, SMEM_TOT);

    k_cvtW<<<NBLK, 256>>>(W_src, W_dst, b_src, b_dst);
    k_h0<<<(NN * 64 + 255) / 256, 256>>>(feat, W_in, b_in, dst);
    k_scan1<<<NBLK, 256>>>();
    k_scan3<<<NBLK, 256>>>();
    k_scatter<<<(EE + 255) / 256, 256>>>(src, dst);

    const int nrb = (NN + 127) / 128;   // 391 row blocks
    k_mma<<<nrb, 256, SMEM_TOT>>>(0);   // launch 5: g_gc = h0@Wbot + bias
    for (int L = 0; L < 4; L++) {
        k_mma<<<nrb, 256, SMEM_TOT>>>(L == 0 ? 1 : 2);
        k_agg<<<(NN * 32 + 255) / 256, 256>>>(attn, L == 3 ? 1 : 0);
    }

    k_pool<<<200, 256>>>(is_root, gid);
    k_out<<<1, 512>>>(W_out, b_out, out);
}

// round 12
// speedup vs baseline: 1.6222x; 1.6222x over previous
#include <cuda_runtime.h>
#include <cuda_fp16.h>
#include <stdint.h>
#include <cstdint>
#include <math.h>

#define NN 50000
#define EE 400000
#define BG 16
#define HD 256      // fs / fd columns
#define NBLK ((NN + 256) / 256)   // 196 scan blocks

// 16B-chunk XOR swizzle on 128B rows (64 halves): conflict-free ldmatrix
#define SWZ(r, c8) (((r) << 7) | ((((c8) ^ ((r) & 7))) << 4))
#define ATILE 16384                 // one 128x64-half tile, bytes
#define SMEM_A (2 * ATILE)          // 32 KB (up to 2 A tiles)
#define SMEM_B (2 * ATILE)          // 32 KB per buffer (up to 2 W tiles)
#define SMEM_TOT (SMEM_A + 2 * SMEM_B)   // 96 KB -> 2 CTAs/SM

// ---------------- device scratch (static globals: no allocation) -------------
__device__ __align__(16) float g_hfin[NN * 64];
__device__ __align__(16) __half g_fsh[NN * HD];    // 25.6 MB
__device__ __align__(16) __half g_fdh[NN * HD];    // 25.6 MB
__device__ __align__(16) __half g_Ah[NN * 64];     // h   (layers 1-3 input)
__device__ __align__(16) __half g_A0h[NN * 64];    // h0
__device__ __align__(16) __half g_Wt[512 * 64];    // W_top   [n][k]
__device__ __align__(16) __half g_Wb[512 * 64];    // W_bot
__device__ __align__(16) __half g_Wc[512 * 64];    // W_top + W_bot (layer 0)
__device__ __align__(16) float g_bias2[512];
__device__ int   g_rowoff[NN + 1];
__device__ int   g_cursor[NN];
__device__ int   g_esrc[EE];
__device__ int   g_bsum[NBLK];
__device__ float g_hg[BG * 64];

// ---------------- asm helpers -------------------------------------------------
__device__ __forceinline__ uint32_t s2u(const void* p) {
    uint32_t a;
    asm("{ .reg .u64 t; cvta.to.shared.u64 t, %1; cvt.u32.u64 %0, t; }"
        : "=r"(a) : "l"(p));
    return a;
}
__device__ __forceinline__ void cpa16(uint32_t dst, const void* src) {
    asm volatile("cp.async.cg.shared.global [%0], [%1], 16;" :: "r"(dst), "l"(src));
}
#define CPA_COMMIT() asm volatile("cp.async.commit_group;" ::: "memory")
#define CPA_WAIT0()  asm volatile("cp.async.wait_group 0;" ::: "memory")

__device__ __forceinline__ void ldsm_x4(uint32_t& r0, uint32_t& r1, uint32_t& r2,
                                        uint32_t& r3, uint32_t addr) {
    asm volatile("ldmatrix.sync.aligned.m8n8.x4.shared.b16 {%0,%1,%2,%3}, [%4];"
                 : "=r"(r0), "=r"(r1), "=r"(r2), "=r"(r3) : "r"(addr));
}
__device__ __forceinline__ void mma16816h(float* d, const uint32_t* a,
                                          uint32_t b0, uint32_t b1) {
    asm volatile(
        "mma.sync.aligned.m16n8k16.row.col.f32.f16.f16.f32 "
        "{%0,%1,%2,%3}, {%4,%5,%6,%7}, {%8,%9}, {%0,%1,%2,%3};"
        : "+f"(d[0]), "+f"(d[1]), "+f"(d[2]), "+f"(d[3])
        : "r"(a[0]), "r"(a[1]), "r"(a[2]), "r"(a[3]), "r"(b0), "r"(b1));
}

__device__ __forceinline__ void unp8(const uint4& u, float* f) {
    const __half2* hp = (const __half2*)&u;
    float2 a = __half22float2(hp[0]), b = __half22float2(hp[1]);
    float2 c = __half22float2(hp[2]), d = __half22float2(hp[3]);
    f[0] = a.x; f[1] = a.y; f[2] = b.x; f[3] = b.y;
    f[4] = c.x; f[5] = c.y; f[6] = d.x; f[7] = d.y;
}

// ---------------- fused setup kernels -----------------------------------------
__global__ void k_cvtW(const float* __restrict__ Ws, const float* __restrict__ Wd,
                       const float* __restrict__ bs, const float* __restrict__ bd) {
    int idx = blockIdx.x * blockDim.x + threadIdx.x;
    if (idx <= NN) g_rowoff[idx] = 0;
    if (idx < BG * 64) g_hg[idx] = 0.f;
    if (idx >= 512 * 64) return;
    int n = idx >> 6, k = idx & 63;
    float wt = (n < 256) ? Ws[k * 256 + n] : Wd[k * 256 + (n - 256)];
    float wb = (n < 256) ? Ws[(k + 64) * 256 + n] : Wd[(k + 64) * 256 + (n - 256)];
    g_Wt[idx] = __float2half(wt);
    g_Wb[idx] = __float2half(wb);
    g_Wc[idx] = __float2half(wt + wb);
    if (idx < 512) g_bias2[idx] = (idx < 256) ? bs[idx] : bd[idx - 256];
}

// h0 tiles (fp16) + degree histogram
__global__ void k_h0(const float* __restrict__ feat, const float* __restrict__ W_in,
                     const float* __restrict__ b_in, const int* __restrict__ dst) {
    int idx = blockIdx.x * blockDim.x + threadIdx.x;
    if (idx >= NN * 64) return;
    if (idx < EE) atomicAdd(&g_rowoff[dst[idx] + 1], 1);
    int i = idx >> 6, d = idx & 63;
    const float4* f4 = (const float4*)(feat + i * 16);
    float4 f0 = f4[0], f1 = f4[1], f2 = f4[2], f3 = f4[3];
    float s = b_in[d];
    s = fmaf(f0.x, W_in[0 * 64 + d], s);  s = fmaf(f0.y, W_in[1 * 64 + d], s);
    s = fmaf(f0.z, W_in[2 * 64 + d], s);  s = fmaf(f0.w, W_in[3 * 64 + d], s);
    s = fmaf(f1.x, W_in[4 * 64 + d], s);  s = fmaf(f1.y, W_in[5 * 64 + d], s);
    s = fmaf(f1.z, W_in[6 * 64 + d], s);  s = fmaf(f1.w, W_in[7 * 64 + d], s);
    s = fmaf(f2.x, W_in[8 * 64 + d], s);  s = fmaf(f2.y, W_in[9 * 64 + d], s);
    s = fmaf(f2.z, W_in[10 * 64 + d], s); s = fmaf(f2.w, W_in[11 * 64 + d], s);
    s = fmaf(f3.x, W_in[12 * 64 + d], s); s = fmaf(f3.y, W_in[13 * 64 + d], s);
    s = fmaf(f3.z, W_in[14 * 64 + d], s); s = fmaf(f3.w, W_in[15 * 64 + d], s);
    g_A0h[idx] = __float2half(s);
}

// ---------------- parallel CSR scan -------------------------------------------
__global__ void k_scan1() {
    __shared__ int ws[8];
    int b = blockIdx.x, t = threadIdx.x;
    int lane = t & 31, w = t >> 5;
    int idx = b * 256 + t;
    int x = (idx <= NN) ? g_rowoff[idx] : 0;
#pragma unroll
    for (int off = 1; off < 32; off <<= 1) {
        int y = __shfl_up_sync(0xffffffffu, x, off);
        if (lane >= off) x += y;
    }
    if (lane == 31) ws[w] = x;
    __syncthreads();
    if (w == 0 && lane < 8) {
        int v = ws[lane];
#pragma unroll
        for (int off = 1; off < 8; off <<= 1) {
            int y = __shfl_up_sync(0x000000ffu, v, off, 8);
            if (lane >= off) v += y;
        }
        ws[lane] = v;
    }
    __syncthreads();
    int add = w ? ws[w - 1] : 0;
    x += add;
    if (idx <= NN) g_rowoff[idx] = x;
    if (t == 255) g_bsum[b] = x;
}

__global__ void k_scan3() {
    __shared__ int ws[8];
    int b = blockIdx.x, t = threadIdx.x;
    int lane = t & 31, w = t >> 5;
    int v = (t < b && t < NBLK) ? g_bsum[t] : 0;
#pragma unroll
    for (int off = 16; off > 0; off >>= 1)
        v += __shfl_xor_sync(0xffffffffu, v, off);
    if (lane == 0) ws[w] = v;
    __syncthreads();
    if (t == 0) {
        int s = 0;
#pragma unroll
        for (int i = 0; i < 8; i++) s += ws[i];
        ws[0] = s;
    }
    __syncthreads();
    int add = ws[0];
    int idx = b * 256 + t;
    if (idx <= NN) {
        int r = g_rowoff[idx] + add;
        g_rowoff[idx] = r;
        if (idx < NN) g_cursor[idx] = r;
    }
}

__global__ void k_scatter(const int* __restrict__ src, const int* __restrict__ dst) {
    int e = blockIdx.x * blockDim.x + threadIdx.x;
    if (e < EE) {
        int d = dst[e];
        int p = atomicAdd(&g_cursor[d], 1);
        g_esrc[p] = src[e];
    }
}

// ---------------- fp16 HMMA GEMM (persistent over N, cp.async db B) -----------
// mode 0 (layer 0):   fsd = A0 @ Wc + bias        (1 segment)
// mode 1 (layers1-3): fsd = A @ Wt + A0 @ Wb + bias  (2 segments)
__device__ __forceinline__ void do_seg(uint32_t aBase, uint32_t bBase,
                                       float (&acc)[2][8][4],
                                       int wm, int wn, int a_lrow, int a_c8,
                                       int b_lrow, int b_c8) {
#pragma unroll
    for (int k16 = 0; k16 < 4; k16++) {
        int kc8 = k16 * 2;
        uint32_t af[2][4];
#pragma unroll
        for (int mt = 0; mt < 2; mt++) {
            int r = wm + mt * 16 + a_lrow;
            ldsm_x4(af[mt][0], af[mt][1], af[mt][2], af[mt][3],
                    aBase + SWZ(r, kc8 + a_c8));
        }
        uint32_t bf[4][4];
#pragma unroll
        for (int p = 0; p < 4; p++) {
            int r = wn + p * 16 + b_lrow;
            ldsm_x4(bf[p][0], bf[p][1], bf[p][2], bf[p][3],
                    bBase + SWZ(r, kc8 + b_c8));
        }
#pragma unroll
        for (int mt = 0; mt < 2; mt++)
#pragma unroll
            for (int nt = 0; nt < 8; nt++)
                mma16816h(acc[mt][nt], af[mt],
                          bf[nt >> 1][(nt & 1) * 2], bf[nt >> 1][(nt & 1) * 2 + 1]);
    }
}

__global__ void __launch_bounds__(256, 2) k_mma(int mode) {
    extern __shared__ char sm[];
    const int tid = threadIdx.x;
    const int lane = tid & 31;
    const int wid = tid >> 5;
    const int wm = (wid >> 1) * 32;
    const int wn = (wid & 1) * 64;
    const int row0 = blockIdx.x * 128;

    const uint32_t uA = s2u(sm);
    const uint32_t uB = uA + SMEM_A;

    const __half* asrc[2];
    const __half* bsrc[2];
    int nt_;
    if (mode) { asrc[0] = g_Ah;  asrc[1] = g_A0h; bsrc[0] = g_Wt; bsrc[1] = g_Wb; nt_ = 2; }
    else      { asrc[0] = g_A0h;                  bsrc[0] = g_Wc;                 nt_ = 1; }

    for (int a = 0; a < nt_; a++) {
        const __half* s = asrc[a];
        uint32_t base = uA + a * ATILE;
#pragma unroll
        for (int it = 0; it < 4; it++) {
            int idx = tid + 256 * it;
            int r = idx >> 3, c8 = idx & 7;
            int grow = row0 + r;
            if (grow < NN)
                cpa16(base + SWZ(r, c8), s + (size_t)grow * 64 + c8 * 8);
            else
                *(float4*)(sm + a * ATILE + SWZ(r, c8)) = make_float4(0.f, 0.f, 0.f, 0.f);
        }
    }
    for (int b = 0; b < nt_; b++) {
        const __half* s = bsrc[b];
        uint32_t base = uB + b * ATILE;
#pragma unroll
        for (int it = 0; it < 4; it++) {
            int idx = tid + 256 * it;
            int r = idx >> 3, c8 = idx & 7;
            cpa16(base + SWZ(r, c8), s + (size_t)r * 64 + c8 * 8);
        }
    }
    CPA_COMMIT();
    CPA_WAIT0();
    __syncthreads();

    const int a_lrow = lane & 15;
    const int a_c8 = lane >> 4;
    const int b_lrow = (lane & 7) + ((lane >> 4) << 3);
    const int b_c8 = (lane & 8) >> 3;

#pragma unroll
    for (int blk = 0; blk < 4; blk++) {
        const uint32_t bBuf = uB + (blk & 1) * SMEM_B;

        if (blk < 3) {
            uint32_t nBuf = uB + ((blk + 1) & 1) * SMEM_B;
            int nrow0 = (blk + 1) * 128;
            for (int b = 0; b < nt_; b++) {
                const __half* s = bsrc[b] + (size_t)nrow0 * 64;
                uint32_t base = nBuf + b * ATILE;
#pragma unroll
                for (int it = 0; it < 4; it++) {
                    int idx = tid + 256 * it;
                    int r = idx >> 3, c8 = idx & 7;
                    cpa16(base + SWZ(r, c8), s + (size_t)r * 64 + c8 * 8);
                }
            }
            CPA_COMMIT();
        }

        float acc[2][8][4];
#pragma unroll
        for (int mt = 0; mt < 2; mt++)
#pragma unroll
            for (int nt = 0; nt < 8; nt++)
#pragma unroll
                for (int j = 0; j < 4; j++) acc[mt][nt][j] = 0.f;

        do_seg(uA, bBuf, acc, wm, wn, a_lrow, a_c8, b_lrow, b_c8);
        if (mode)
            do_seg(uA + ATILE, bBuf + ATILE, acc, wm, wn, a_lrow, a_c8, b_lrow, b_c8);

        // ---- epilogue: + bias, convert fp16, write fs (cols<256) or fd ----
        {
            int col0 = blk * 128;
            __half* Cb = (col0 < 256) ? g_fsh : g_fdh;
            const int cb0 = (col0 < 256) ? col0 : col0 - 256;
#pragma unroll
            for (int nt = 0; nt < 8; nt++) {
                int gcol = col0 + wn + nt * 8 + (lane & 3) * 2;
                float b0 = g_bias2[gcol], b1 = g_bias2[gcol + 1];
                int cc = cb0 + wn + nt * 8 + (lane & 3) * 2;
#pragma unroll
                for (int mt = 0; mt < 2; mt++) {
                    int rr = row0 + wm + mt * 16 + (lane >> 2);
                    if (rr < NN)
                        *(__half2*)&Cb[(size_t)rr * HD + cc] =
                            __floats2half2_rn(acc[mt][nt][0] + b0, acc[mt][nt][1] + b1);
                    if (rr + 8 < NN)
                        *(__half2*)&Cb[(size_t)(rr + 8) * HD + cc] =
                            __floats2half2_rn(acc[mt][nt][2] + b0, acc[mt][nt][3] + b1);
                }
            }
        }

        if (blk < 3) {
            CPA_WAIT0();
            __syncthreads();
        }
    }
}

// ---------------- edge aggregation: one warp per node, 4-edge batches ---------
__global__ void __launch_bounds__(256) k_agg(const float* __restrict__ attn, int last) {
    int gw = (blockIdx.x * blockDim.x + threadIdx.x) >> 5;
    int lane = threadIdx.x & 31;
    if (gw >= NN) return;

    int base = lane * 8;
    float fd[8], at[8];
    {
        uint4 u = *(const uint4*)(g_fdh + (size_t)gw * HD + base);
        unp8(u, fd);
        float4 atA = *(const float4*)(attn + base);
        float4 atB = *(const float4*)(attn + base + 4);
        at[0] = atA.x; at[1] = atA.y; at[2] = atA.z; at[3] = atA.w;
        at[4] = atB.x; at[5] = atB.y; at[6] = atB.z; at[7] = atB.w;
    }

    float m = -1e30f, denom = 0.f;
    float acc[8];
#pragma unroll
    for (int j = 0; j < 8; j++) acc[j] = 0.f;

    int e0 = g_rowoff[gw], e1 = g_rowoff[gw + 1];
    for (int e = e0; e < e1; e += 4) {
        int n = e1 - e;
        int s0 = g_esrc[e];
        int s1 = (n > 1) ? g_esrc[e + 1] : s0;
        int s2 = (n > 2) ? g_esrc[e + 2] : s0;
        int s3 = (n > 3) ? g_esrc[e + 3] : s0;
        uint4 u0 = *(const uint4*)(g_fsh + (size_t)s0 * HD + base);
        uint4 u1 = *(const uint4*)(g_fsh + (size_t)s1 * HD + base);
        uint4 u2 = *(const uint4*)(g_fsh + (size_t)s2 * HD + base);
        uint4 u3 = *(const uint4*)(g_fsh + (size_t)s3 * HD + base);

        float f0[8], f1[8], f2[8], f3[8];
        unp8(u0, f0); unp8(u1, f1); unp8(u2, f2); unp8(u3, f3);

        float p0 = 0.f, p1 = 0.f, p2 = 0.f, p3 = 0.f;
#pragma unroll
        for (int j = 0; j < 8; j++) {
            float v;
            v = f0[j] + fd[j]; v = (v > 0.f) ? v : 0.2f * v; p0 = fmaf(v, at[j], p0);
            v = f1[j] + fd[j]; v = (v > 0.f) ? v : 0.2f * v; p1 = fmaf(v, at[j], p1);
            v = f2[j] + fd[j]; v = (v > 0.f) ? v : 0.2f * v; p2 = fmaf(v, at[j], p2);
            v = f3[j] + fd[j]; v = (v > 0.f) ? v : 0.2f * v; p3 = fmaf(v, at[j], p3);
        }
#pragma unroll
        for (int off = 1; off < 8; off <<= 1) {
            p0 += __shfl_xor_sync(0xffffffffu, p0, off);
            p1 += __shfl_xor_sync(0xffffffffu, p1, off);
            p2 += __shfl_xor_sync(0xffffffffu, p2, off);
            p3 += __shfl_xor_sync(0xffffffffu, p3, off);
        }
        if (n < 2) p1 = -1e30f;
        if (n < 3) p2 = -1e30f;
        if (n < 4) p3 = -1e30f;

        float mb = fmaxf(fmaxf(p0, p1), fmaxf(p2, p3));
        float nm = fmaxf(m, mb);
        float sc = __expf(m - nm);
        float w0 = __expf(p0 - nm);
        float w1 = __expf(p1 - nm);
        float w2 = __expf(p2 - nm);
        float w3 = __expf(p3 - nm);
        m = nm;
        denom = fmaf(denom, sc, (w0 + w1) + (w2 + w3));
#pragma unroll
        for (int j = 0; j < 8; j++) {
            float s = fmaf(w0, f0[j], w1 * f1[j]);
            s = fmaf(w2, f2[j], s);
            s = fmaf(w3, f3[j], s);
            acc[j] = fmaf(acc[j], sc, s);
        }
    }

    float inv = (denom > 0.f) ? (1.f / denom) : 0.f;
    float t[8];
#pragma unroll
    for (int j = 0; j < 8; j++) t[j] = tanhf(acc[j] * inv);
#pragma unroll
    for (int j = 0; j < 8; j++) {
        t[j] += __shfl_xor_sync(0xffffffffu, t[j], 8);
        t[j] += __shfl_xor_sync(0xffffffffu, t[j], 16);
    }
    if (lane < 8) {
        size_t ofs = (size_t)gw * 64 + lane * 8;
        if (last) {
            float* hout = g_hfin + ofs;
#pragma unroll
            for (int j = 0; j < 8; j++) hout[j] = t[j];
        } else {
            uint4 w;
            __half2* hp = (__half2*)&w;
            hp[0] = __floats2half2_rn(t[0], t[1]);
            hp[1] = __floats2half2_rn(t[2], t[3]);
            hp[2] = __floats2half2_rn(t[4], t[5]);
            hp[3] = __floats2half2_rn(t[6], t[7]);
            *(uint4*)(g_Ah + ofs) = w;
        }
    }
}

// ---------------- graph pooling + output head --------------------------------
__global__ void k_pool(const float* __restrict__ is_root, const int* __restrict__ gid) {
    __shared__ float sh[BG * 64];
    int t = threadIdx.x;
    for (int x = t; x < BG * 64; x += 256) sh[x] = 0.f;
    __syncthreads();
    for (int idx = blockIdx.x * 256 + t; idx < NN * 64; idx += gridDim.x * 256) {
        int i = idx >> 6, d = idx & 63;
        atomicAdd(&sh[(gid[i] << 6) | d], g_hfin[idx] * is_root[i]);
    }
    __syncthreads();
    for (int x = t; x < BG * 64; x += 256) atomicAdd(&g_hg[x], sh[x]);
}

__global__ void k_out(const float* __restrict__ W_out, const float* __restrict__ b_out,
                      float* __restrict__ out) {
    int t = threadIdx.x;
    if (t >= BG * 32) return;
    int b = t >> 5, j = t & 31;
    float s = b_out[j];
#pragma unroll
    for (int d = 0; d < 64; d++) s = fmaf(g_hg[b * 64 + d], W_out[d * 32 + j], s);
    out[t] = s;
}

// ---------------- launcher ----------------------------------------------------
extern "C" void kernel_launch(void* const* d_in, const int* in_sizes, int n_in,
                              void* d_out, int out_size) {
    const float* feat    = (const float*)d_in[0];
    const float* is_root = (const float*)d_in[1];
    const int*   src     = (const int*)  d_in[2];
    const int*   dst     = (const int*)  d_in[3];
    const int*   gid     = (const int*)  d_in[4];
    const float* W_in    = (const float*)d_in[5];
    const float* b_in    = (const float*)d_in[6];
    const float* W_src   = (const float*)d_in[7];
    const float* b_src   = (const float*)d_in[8];
    const float* W_dst   = (const float*)d_in[9];
    const float* b_dst   = (const float*)d_in[10];
    const float* attn    = (const float*)d_in[11];
    const float* W_out   = (const float*)d_in[12];
    const float* b_out   = (const float*)d_in[13];
    float* out = (float*)d_out;

    cudaFuncSetAttribute(k_mma, cudaFuncAttributeMaxDynamicSharedMemorySize, SMEM_TOT);

    const int nrb = (NN + 127) / 128;   // 391 row blocks

    // indices 0-2: weights (+zero), h0+hist, scan1
    k_cvtW<<<NBLK, 256>>>(W_src, W_dst, b_src, b_dst);
    k_h0<<<(NN * 64 + 255) / 256, 256>>>(feat, W_in, b_in, dst);
    k_scan1<<<NBLK, 256>>>();
    // index 3: layer-0 GEMM (needs only weights + h0) -> profiled by ncu
    k_mma<<<nrb, 256, SMEM_TOT>>>(0);
    // finish CSR while GEMM result is consumed next
    k_scan3<<<NBLK, 256>>>();
    k_scatter<<<(EE + 255) / 256, 256>>>(src, dst);

    k_agg<<<(NN * 32 + 255) / 256, 256>>>(attn, 0);          // layer 0 agg
    for (int L = 1; L < 4; L++) {
        k_mma<<<nrb, 256, SMEM_TOT>>>(1);
        k_agg<<<(NN * 32 + 255) / 256, 256>>>(attn, L == 3 ? 1 : 0);
    }

    k_pool<<<200, 256>>>(is_root, gid);
    k_out<<<1, 512>>>(W_out, b_out, out);
}

// round 13
// speedup vs baseline: 1.6914x; 1.0426x over previous
#include <cuda_runtime.h>
#include <cuda_fp16.h>
#include <stdint.h>
#include <cstdint>
#include <math.h>

#define NN 50000
#define EE 400000
#define BG 16
#define HD 256      // fs / fd columns
#define NBLK ((NN + 256) / 256)   // 196 scan blocks

// 16B-chunk XOR swizzle on 128B rows (64 halves): conflict-free ldmatrix
#define SWZ(r, c8) (((r) << 7) | ((((c8) ^ ((r) & 7))) << 4))
#define ATILE 16384                 // one 128x64-half tile, bytes
#define SMEM_A (2 * ATILE)          // 32 KB (up to 2 A tiles)
#define SMEM_B (2 * ATILE)          // 32 KB per buffer (up to 2 W tiles)
#define SMEM_TOT (SMEM_A + 2 * SMEM_B)   // 96 KB -> 2 CTAs/SM

// ---------------- device scratch (static globals: no allocation) -------------
__device__ __align__(16) float g_hfin[NN * 64];
__device__ __align__(16) __half g_fsh[NN * HD];    // 25.6 MB
__device__ __align__(16) __half g_fdh[NN * HD];    // 25.6 MB
__device__ __align__(16) __half g_Ah[NN * 64];     // h   (layers 1-3 input)
__device__ __align__(16) __half g_A0h[NN * 64];    // h0
__device__ __align__(16) __half g_Wt[512 * 64];    // W_top   [n][k]
__device__ __align__(16) __half g_Wb[512 * 64];    // W_bot
__device__ __align__(16) __half g_Wc[512 * 64];    // W_top + W_bot (layer 0)
__device__ __align__(16) float g_bias2[512];
__device__ int   g_rowoff[NN + 1];
__device__ int   g_cursor[NN];
__device__ int   g_esrc[EE];
__device__ int   g_bsum[NBLK];
__device__ float g_hg[BG * 64];

// ---------------- asm helpers -------------------------------------------------
__device__ __forceinline__ uint32_t s2u(const void* p) {
    uint32_t a;
    asm("{ .reg .u64 t; cvta.to.shared.u64 t, %1; cvt.u32.u64 %0, t; }"
        : "=r"(a) : "l"(p));
    return a;
}
__device__ __forceinline__ void cpa16(uint32_t dst, const void* src) {
    asm volatile("cp.async.cg.shared.global [%0], [%1], 16;" :: "r"(dst), "l"(src));
}
#define CPA_COMMIT() asm volatile("cp.async.commit_group;" ::: "memory")
#define CPA_WAIT0()  asm volatile("cp.async.wait_group 0;" ::: "memory")

__device__ __forceinline__ void ldsm_x4(uint32_t& r0, uint32_t& r1, uint32_t& r2,
                                        uint32_t& r3, uint32_t addr) {
    asm volatile("ldmatrix.sync.aligned.m8n8.x4.shared.b16 {%0,%1,%2,%3}, [%4];"
                 : "=r"(r0), "=r"(r1), "=r"(r2), "=r"(r3) : "r"(addr));
}
__device__ __forceinline__ void mma16816h(float* d, const uint32_t* a,
                                          uint32_t b0, uint32_t b1) {
    asm volatile(
        "mma.sync.aligned.m16n8k16.row.col.f32.f16.f16.f32 "
        "{%0,%1,%2,%3}, {%4,%5,%6,%7}, {%8,%9}, {%0,%1,%2,%3};"
        : "+f"(d[0]), "+f"(d[1]), "+f"(d[2]), "+f"(d[3])
        : "r"(a[0]), "r"(a[1]), "r"(a[2]), "r"(a[3]), "r"(b0), "r"(b1));
}

__device__ __forceinline__ void unp8(const uint4& u, float* f) {
    const __half2* hp = (const __half2*)&u;
    float2 a = __half22float2(hp[0]), b = __half22float2(hp[1]);
    float2 c = __half22float2(hp[2]), d = __half22float2(hp[3]);
    f[0] = a.x; f[1] = a.y; f[2] = b.x; f[3] = b.y;
    f[4] = c.x; f[5] = c.y; f[6] = d.x; f[7] = d.y;
}

// ---------------- fused setup kernels -----------------------------------------
__global__ void k_cvtW(const float* __restrict__ Ws, const float* __restrict__ Wd,
                       const float* __restrict__ bs, const float* __restrict__ bd) {
    int idx = blockIdx.x * blockDim.x + threadIdx.x;
    if (idx <= NN) g_rowoff[idx] = 0;
    if (idx < BG * 64) g_hg[idx] = 0.f;
    if (idx >= 512 * 64) return;
    int n = idx >> 6, k = idx & 63;
    float wt = (n < 256) ? Ws[k * 256 + n] : Wd[k * 256 + (n - 256)];
    float wb = (n < 256) ? Ws[(k + 64) * 256 + n] : Wd[(k + 64) * 256 + (n - 256)];
    g_Wt[idx] = __float2half(wt);
    g_Wb[idx] = __float2half(wb);
    g_Wc[idx] = __float2half(wt + wb);
    if (idx < 512) g_bias2[idx] = (idx < 256) ? bs[idx] : bd[idx - 256];
}

// h0 tiles (fp16) + degree histogram
__global__ void k_h0(const float* __restrict__ feat, const float* __restrict__ W_in,
                     const float* __restrict__ b_in, const int* __restrict__ dst) {
    int idx = blockIdx.x * blockDim.x + threadIdx.x;
    if (idx >= NN * 64) return;
    if (idx < EE) atomicAdd(&g_rowoff[dst[idx] + 1], 1);
    int i = idx >> 6, d = idx & 63;
    const float4* f4 = (const float4*)(feat + i * 16);
    float4 f0 = f4[0], f1 = f4[1], f2 = f4[2], f3 = f4[3];
    float s = b_in[d];
    s = fmaf(f0.x, W_in[0 * 64 + d], s);  s = fmaf(f0.y, W_in[1 * 64 + d], s);
    s = fmaf(f0.z, W_in[2 * 64 + d], s);  s = fmaf(f0.w, W_in[3 * 64 + d], s);
    s = fmaf(f1.x, W_in[4 * 64 + d], s);  s = fmaf(f1.y, W_in[5 * 64 + d], s);
    s = fmaf(f1.z, W_in[6 * 64 + d], s);  s = fmaf(f1.w, W_in[7 * 64 + d], s);
    s = fmaf(f2.x, W_in[8 * 64 + d], s);  s = fmaf(f2.y, W_in[9 * 64 + d], s);
    s = fmaf(f2.z, W_in[10 * 64 + d], s); s = fmaf(f2.w, W_in[11 * 64 + d], s);
    s = fmaf(f3.x, W_in[12 * 64 + d], s); s = fmaf(f3.y, W_in[13 * 64 + d], s);
    s = fmaf(f3.z, W_in[14 * 64 + d], s); s = fmaf(f3.w, W_in[15 * 64 + d], s);
    g_A0h[idx] = __float2half(s);
}

// ---------------- parallel CSR scan -------------------------------------------
__global__ void k_scan1() {
    __shared__ int ws[8];
    int b = blockIdx.x, t = threadIdx.x;
    int lane = t & 31, w = t >> 5;
    int idx = b * 256 + t;
    int x = (idx <= NN) ? g_rowoff[idx] : 0;
#pragma unroll
    for (int off = 1; off < 32; off <<= 1) {
        int y = __shfl_up_sync(0xffffffffu, x, off);
        if (lane >= off) x += y;
    }
    if (lane == 31) ws[w] = x;
    __syncthreads();
    if (w == 0 && lane < 8) {
        int v = ws[lane];
#pragma unroll
        for (int off = 1; off < 8; off <<= 1) {
            int y = __shfl_up_sync(0x000000ffu, v, off, 8);
            if (lane >= off) v += y;
        }
        ws[lane] = v;
    }
    __syncthreads();
    int add = w ? ws[w - 1] : 0;
    x += add;
    if (idx <= NN) g_rowoff[idx] = x;
    if (t == 255) g_bsum[b] = x;
}

__global__ void k_scan3() {
    __shared__ int ws[8];
    int b = blockIdx.x, t = threadIdx.x;
    int lane = t & 31, w = t >> 5;
    int v = (t < b && t < NBLK) ? g_bsum[t] : 0;
#pragma unroll
    for (int off = 16; off > 0; off >>= 1)
        v += __shfl_xor_sync(0xffffffffu, v, off);
    if (lane == 0) ws[w] = v;
    __syncthreads();
    if (t == 0) {
        int s = 0;
#pragma unroll
        for (int i = 0; i < 8; i++) s += ws[i];
        ws[0] = s;
    }
    __syncthreads();
    int add = ws[0];
    int idx = b * 256 + t;
    if (idx <= NN) {
        int r = g_rowoff[idx] + add;
        g_rowoff[idx] = r;
        if (idx < NN) g_cursor[idx] = r;
    }
}

__global__ void k_scatter(const int* __restrict__ src, const int* __restrict__ dst) {
    int e = blockIdx.x * blockDim.x + threadIdx.x;
    if (e < EE) {
        int d = dst[e];
        int p = atomicAdd(&g_cursor[d], 1);
        g_esrc[p] = src[e];
    }
}

// ---------------- fp16 HMMA GEMM ------------------------------------------------
// grid (2, nrb): blockIdx.y = 128-row block; blockIdx.x = half:
//   half 0 -> global cols 0..255  -> g_fsh
//   half 1 -> global cols 256..511-> g_fdh
// Each CTA loops over its 2 col-blocks with double-buffered B.
// mode 0 (layer 0):   fsd = A0 @ Wc + bias          (1 segment)
// mode 1 (layers1-3): fsd = A @ Wt + A0 @ Wb + bias (2 segments)
__device__ __forceinline__ void do_seg(uint32_t aBase, uint32_t bBase,
                                       float (&acc)[2][8][4],
                                       int wm, int wn, int a_lrow, int a_c8,
                                       int b_lrow, int b_c8) {
#pragma unroll
    for (int k16 = 0; k16 < 4; k16++) {
        int kc8 = k16 * 2;
        uint32_t af[2][4];
#pragma unroll
        for (int mt = 0; mt < 2; mt++) {
            int r = wm + mt * 16 + a_lrow;
            ldsm_x4(af[mt][0], af[mt][1], af[mt][2], af[mt][3],
                    aBase + SWZ(r, kc8 + a_c8));
        }
        uint32_t bf[4][4];
#pragma unroll
        for (int p = 0; p < 4; p++) {
            int r = wn + p * 16 + b_lrow;
            ldsm_x4(bf[p][0], bf[p][1], bf[p][2], bf[p][3],
                    bBase + SWZ(r, kc8 + b_c8));
        }
#pragma unroll
        for (int mt = 0; mt < 2; mt++)
#pragma unroll
            for (int nt = 0; nt < 8; nt++)
                mma16816h(acc[mt][nt], af[mt],
                          bf[nt >> 1][(nt & 1) * 2], bf[nt >> 1][(nt & 1) * 2 + 1]);
    }
}

__global__ void __launch_bounds__(256, 2) k_mma(int mode) {
    extern __shared__ char sm[];
    const int tid = threadIdx.x;
    const int lane = tid & 31;
    const int wid = tid >> 5;
    const int wm = (wid >> 1) * 32;
    const int wn = (wid & 1) * 64;
    const int row0 = blockIdx.y * 128;
    const int half = blockIdx.x;          // 0: fs, 1: fd

    const uint32_t uA = s2u(sm);
    const uint32_t uB = uA + SMEM_A;

    const __half* asrc[2];
    const __half* bsrc[2];
    int nt_;
    if (mode) { asrc[0] = g_Ah;  asrc[1] = g_A0h; bsrc[0] = g_Wt; bsrc[1] = g_Wb; nt_ = 2; }
    else      { asrc[0] = g_A0h;                  bsrc[0] = g_Wc;                 nt_ = 1; }

    // stage A tiles (once) + B for first col-block of this half
    for (int a = 0; a < nt_; a++) {
        const __half* s = asrc[a];
        uint32_t base = uA + a * ATILE;
#pragma unroll
        for (int it = 0; it < 4; it++) {
            int idx = tid + 256 * it;
            int r = idx >> 3, c8 = idx & 7;
            int grow = row0 + r;
            if (grow < NN)
                cpa16(base + SWZ(r, c8), s + (size_t)grow * 64 + c8 * 8);
            else
                *(float4*)(sm + a * ATILE + SWZ(r, c8)) = make_float4(0.f, 0.f, 0.f, 0.f);
        }
    }
    for (int b = 0; b < nt_; b++) {
        const __half* s = bsrc[b] + (size_t)(half * 256) * 64;
        uint32_t base = uB + b * ATILE;
#pragma unroll
        for (int it = 0; it < 4; it++) {
            int idx = tid + 256 * it;
            int r = idx >> 3, c8 = idx & 7;
            cpa16(base + SWZ(r, c8), s + (size_t)r * 64 + c8 * 8);
        }
    }
    CPA_COMMIT();
    CPA_WAIT0();
    __syncthreads();

    const int a_lrow = lane & 15;
    const int a_c8 = lane >> 4;
    const int b_lrow = (lane & 7) + ((lane >> 4) << 3);
    const int b_c8 = (lane & 8) >> 3;

    __half* Cb = half ? g_fdh : g_fsh;

#pragma unroll
    for (int blk = 0; blk < 2; blk++) {
        const uint32_t bBuf = uB + (blk & 1) * SMEM_B;

        if (blk < 1) {
            uint32_t nBuf = uB + SMEM_B;
            int nrow0 = (half * 2 + 1) * 128;
            for (int b = 0; b < nt_; b++) {
                const __half* s = bsrc[b] + (size_t)nrow0 * 64;
                uint32_t base = nBuf + b * ATILE;
#pragma unroll
                for (int it = 0; it < 4; it++) {
                    int idx = tid + 256 * it;
                    int r = idx >> 3, c8 = idx & 7;
                    cpa16(base + SWZ(r, c8), s + (size_t)r * 64 + c8 * 8);
                }
            }
            CPA_COMMIT();
        }

        float acc[2][8][4];
#pragma unroll
        for (int mt = 0; mt < 2; mt++)
#pragma unroll
            for (int nt = 0; nt < 8; nt++)
#pragma unroll
                for (int j = 0; j < 4; j++) acc[mt][nt][j] = 0.f;

        do_seg(uA, bBuf, acc, wm, wn, a_lrow, a_c8, b_lrow, b_c8);
        if (mode)
            do_seg(uA + ATILE, bBuf + ATILE, acc, wm, wn, a_lrow, a_c8, b_lrow, b_c8);

        // ---- epilogue: + bias, convert fp16, write ----
        {
            int gcol0 = half * 256 + blk * 128;   // global col base (bias)
            int cc0 = blk * 128;                  // col base within fs/fd
#pragma unroll
            for (int nt = 0; nt < 8; nt++) {
                int gcol = gcol0 + wn + nt * 8 + (lane & 3) * 2;
                float b0 = g_bias2[gcol], b1 = g_bias2[gcol + 1];
                int cc = cc0 + wn + nt * 8 + (lane & 3) * 2;
#pragma unroll
                for (int mt = 0; mt < 2; mt++) {
                    int rr = row0 + wm + mt * 16 + (lane >> 2);
                    if (rr < NN)
                        *(__half2*)&Cb[(size_t)rr * HD + cc] =
                            __floats2half2_rn(acc[mt][nt][0] + b0, acc[mt][nt][1] + b1);
                    if (rr + 8 < NN)
                        *(__half2*)&Cb[(size_t)(rr + 8) * HD + cc] =
                            __floats2half2_rn(acc[mt][nt][2] + b0, acc[mt][nt][3] + b1);
                }
            }
        }

        if (blk < 1) {
            CPA_WAIT0();
            __syncthreads();
        }
    }
}

// ---------------- edge aggregation: one warp per node, 4-edge batches ---------
__global__ void __launch_bounds__(256) k_agg(const float* __restrict__ attn, int last) {
    int gw = (blockIdx.x * blockDim.x + threadIdx.x) >> 5;
    int lane = threadIdx.x & 31;
    if (gw >= NN) return;

    int base = lane * 8;
    float fd[8], at[8];
    {
        uint4 u = *(const uint4*)(g_fdh + (size_t)gw * HD + base);
        unp8(u, fd);
        float4 atA = *(const float4*)(attn + base);
        float4 atB = *(const float4*)(attn + base + 4);
        at[0] = atA.x; at[1] = atA.y; at[2] = atA.z; at[3] = atA.w;
        at[4] = atB.x; at[5] = atB.y; at[6] = atB.z; at[7] = atB.w;
    }

    float m = -1e30f, denom = 0.f;
    float acc[8];
#pragma unroll
    for (int j = 0; j < 8; j++) acc[j] = 0.f;

    int e0 = g_rowoff[gw], e1 = g_rowoff[gw + 1];
    for (int e = e0; e < e1; e += 4) {
        int n = e1 - e;
        int s0 = g_esrc[e];
        int s1 = (n > 1) ? g_esrc[e + 1] : s0;
        int s2 = (n > 2) ? g_esrc[e + 2] : s0;
        int s3 = (n > 3) ? g_esrc[e + 3] : s0;
        uint4 u0 = *(const uint4*)(g_fsh + (size_t)s0 * HD + base);
        uint4 u1 = *(const uint4*)(g_fsh + (size_t)s1 * HD + base);
        uint4 u2 = *(const uint4*)(g_fsh + (size_t)s2 * HD + base);
        uint4 u3 = *(const uint4*)(g_fsh + (size_t)s3 * HD + base);

        float f0[8], f1[8], f2[8], f3[8];
        unp8(u0, f0); unp8(u1, f1); unp8(u2, f2); unp8(u3, f3);

        float p0 = 0.f, p1 = 0.f, p2 = 0.f, p3 = 0.f;
#pragma unroll
        for (int j = 0; j < 8; j++) {
            float v;
            v = f0[j] + fd[j]; v = (v > 0.f) ? v : 0.2f * v; p0 = fmaf(v, at[j], p0);
            v = f1[j] + fd[j]; v = (v > 0.f) ? v : 0.2f * v; p1 = fmaf(v, at[j], p1);
            v = f2[j] + fd[j]; v = (v > 0.f) ? v : 0.2f * v; p2 = fmaf(v, at[j], p2);
            v = f3[j] + fd[j]; v = (v > 0.f) ? v : 0.2f * v; p3 = fmaf(v, at[j], p3);
        }
#pragma unroll
        for (int off = 1; off < 8; off <<= 1) {
            p0 += __shfl_xor_sync(0xffffffffu, p0, off);
            p1 += __shfl_xor_sync(0xffffffffu, p1, off);
            p2 += __shfl_xor_sync(0xffffffffu, p2, off);
            p3 += __shfl_xor_sync(0xffffffffu, p3, off);
        }
        if (n < 2) p1 = -1e30f;
        if (n < 3) p2 = -1e30f;
        if (n < 4) p3 = -1e30f;

        float mb = fmaxf(fmaxf(p0, p1), fmaxf(p2, p3));
        float nm = fmaxf(m, mb);
        float sc = __expf(m - nm);
        float w0 = __expf(p0 - nm);
        float w1 = __expf(p1 - nm);
        float w2 = __expf(p2 - nm);
        float w3 = __expf(p3 - nm);
        m = nm;
        denom = fmaf(denom, sc, (w0 + w1) + (w2 + w3));
#pragma unroll
        for (int j = 0; j < 8; j++) {
            float s = fmaf(w0, f0[j], w1 * f1[j]);
            s = fmaf(w2, f2[j], s);
            s = fmaf(w3, f3[j], s);
            acc[j] = fmaf(acc[j], sc, s);
        }
    }

    float inv = (denom > 0.f) ? (1.f / denom) : 0.f;
    float t[8];
#pragma unroll
    for (int j = 0; j < 8; j++) t[j] = tanhf(acc[j] * inv);
#pragma unroll
    for (int j = 0; j < 8; j++) {
        t[j] += __shfl_xor_sync(0xffffffffu, t[j], 8);
        t[j] += __shfl_xor_sync(0xffffffffu, t[j], 16);
    }
    if (lane < 8) {
        size_t ofs = (size_t)gw * 64 + lane * 8;
        if (last) {
            float* hout = g_hfin + ofs;
#pragma unroll
            for (int j = 0; j < 8; j++) hout[j] = t[j];
        } else {
            uint4 w;
            __half2* hp = (__half2*)&w;
            hp[0] = __floats2half2_rn(t[0], t[1]);
            hp[1] = __floats2half2_rn(t[2], t[3]);
            hp[2] = __floats2half2_rn(t[4], t[5]);
            hp[3] = __floats2half2_rn(t[6], t[7]);
            *(uint4*)(g_Ah + ofs) = w;
        }
    }
}

// ---------------- graph pooling + output head --------------------------------
__global__ void k_pool(const float* __restrict__ is_root, const int* __restrict__ gid) {
    __shared__ float sh[BG * 64];
    int t = threadIdx.x;
    for (int x = t; x < BG * 64; x += 256) sh[x] = 0.f;
    __syncthreads();
    for (int idx = blockIdx.x * 256 + t; idx < NN * 64; idx += gridDim.x * 256) {
        int i = idx >> 6, d = idx & 63;
        atomicAdd(&sh[(gid[i] << 6) | d], g_hfin[idx] * is_root[i]);
    }
    __syncthreads();
    for (int x = t; x < BG * 64; x += 256) atomicAdd(&g_hg[x], sh[x]);
}

__global__ void k_out(const float* __restrict__ W_out, const float* __restrict__ b_out,
                      float* __restrict__ out) {
    int t = threadIdx.x;
    if (t >= BG * 32) return;
    int b = t >> 5, j = t & 31;
    float s = b_out[j];
#pragma unroll
    for (int d = 0; d < 64; d++) s = fmaf(g_hg[b * 64 + d], W_out[d * 32 + j], s);
    out[t] = s;
}

// ---------------- launcher ----------------------------------------------------
extern "C" void kernel_launch(void* const* d_in, const int* in_sizes, int n_in,
                              void* d_out, int out_size) {
    const float* feat    = (const float*)d_in[0];
    const float* is_root = (const float*)d_in[1];
    const int*   src     = (const int*)  d_in[2];
    const int*   dst     = (const int*)  d_in[3];
    const int*   gid     = (const int*)  d_in[4];
    const float* W_in    = (const float*)d_in[5];
    const float* b_in    = (const float*)d_in[6];
    const float* W_src   = (const float*)d_in[7];
    const float* b_src   = (const float*)d_in[8];
    const float* W_dst   = (const float*)d_in[9];
    const float* b_dst   = (const float*)d_in[10];
    const float* attn    = (const float*)d_in[11];
    const float* W_out   = (const float*)d_in[12];
    const float* b_out   = (const float*)d_in[13];
    float* out = (float*)d_out;

    cudaFuncSetAttribute(k_mma, cudaFuncAttributeMaxDynamicSharedMemorySize, SMEM_TOT);

    const int nrb = (NN + 127) / 128;   // 391 row blocks
    dim3 mgrid(2, nrb);                 // halves x row blocks (782 CTAs)

    // indices 0-2: weights (+zero), h0+hist, scan1
    k_cvtW<<<NBLK, 256>>>(W_src, W_dst, b_src, b_dst);
    k_h0<<<(NN * 64 + 255) / 256, 256>>>(feat, W_in, b_in, dst);
    k_scan1<<<NBLK, 256>>>();
    // index 3: layer-0 GEMM (needs only weights + h0) -> profiled by ncu
    k_mma<<<mgrid, 256, SMEM_TOT>>>(0);
    // finish CSR while GEMM result is consumed next
    k_scan3<<<NBLK, 256>>>();
    k_scatter<<<(EE + 255) / 256, 256>>>(src, dst);

    k_agg<<<(NN * 32 + 255) / 256, 256>>>(attn, 0);          // layer 0 agg
    for (int L = 1; L < 4; L++) {
        k_mma<<<mgrid, 256, SMEM_TOT>>>(1);
        k_agg<<<(NN * 32 + 255) / 256, 256>>>(attn, L == 3 ? 1 : 0);
    }

    k_pool<<<200, 256>>>(is_root, gid);
    k_out<<<1, 512>>>(W_out, b_out, out);
}

// round 15
// speedup vs baseline: 1.8674x; 1.1041x over previous
#include <cuda_runtime.h>
#include <cuda_fp16.h>
#include <stdint.h>
#include <cstdint>
#include <math.h>

#define NN 50000
#define EE 400000
#define BG 16
#define HD 256      // fs / fd columns
#define NBLK ((NN + 256) / 256)   // 196 scan blocks

// 16B-chunk XOR swizzle on 128B rows (64 halves): conflict-free ldmatrix
#define SWZ(r, c8) (((r) << 7) | ((((c8) ^ ((r) & 7))) << 4))
#define ATILEA 16384                // A tile: 128 rows x 64 halves
#define BTILE  8192                 // B tile: 64 rows x 64 halves
#define SMEM_A (2 * ATILEA)         // 32 KB (up to 2 A tiles)
#define SMEM_Bb (2 * BTILE)         // 16 KB per buffer (up to 2 W tiles)
#define SMEM_TOT (SMEM_A + 2 * SMEM_Bb)   // 64 KB -> 3 CTAs/SM

// ---------------- device scratch (static globals: no allocation) -------------
__device__ __align__(16) float g_hfin[NN * 64];
__device__ __align__(16) __half g_fsh[NN * HD];    // 25.6 MB
__device__ __align__(16) __half g_fdh[NN * HD];    // 25.6 MB
__device__ __align__(16) __half g_Ah[NN * 64];     // h   (layers 1-3 input)
__device__ __align__(16) __half g_A0h[NN * 64];    // h0
__device__ __align__(16) __half g_Wt[512 * 64];    // W_top   [n][k]
__device__ __align__(16) __half g_Wb[512 * 64];    // W_bot
__device__ __align__(16) __half g_Wc[512 * 64];    // W_top + W_bot (layer 0)
__device__ __align__(16) float g_bias2[512];
__device__ int   g_rowoff[NN + 1];
__device__ int   g_cursor[NN];
__device__ int   g_esrc[EE];
__device__ int   g_bsum[NBLK];
__device__ float g_hg[BG * 64];

// ---------------- asm helpers -------------------------------------------------
__device__ __forceinline__ uint32_t s2u(const void* p) {
    uint32_t a;
    asm("{ .reg .u64 t; cvta.to.shared.u64 t, %1; cvt.u32.u64 %0, t; }"
        : "=r"(a) : "l"(p));
    return a;
}
__device__ __forceinline__ void cpa16(uint32_t dst, const void* src) {
    asm volatile("cp.async.cg.shared.global [%0], [%1], 16;" :: "r"(dst), "l"(src));
}
#define CPA_COMMIT() asm volatile("cp.async.commit_group;" ::: "memory")
#define CPA_WAIT0()  asm volatile("cp.async.wait_group 0;" ::: "memory")

__device__ __forceinline__ void ldsm_x4(uint32_t& r0, uint32_t& r1, uint32_t& r2,
                                        uint32_t& r3, uint32_t addr) {
    asm volatile("ldmatrix.sync.aligned.m8n8.x4.shared.b16 {%0,%1,%2,%3}, [%4];"
                 : "=r"(r0), "=r"(r1), "=r"(r2), "=r"(r3) : "r"(addr));
}
__device__ __forceinline__ void mma16816h(float* d, const uint32_t* a,
                                          uint32_t b0, uint32_t b1) {
    asm volatile(
        "mma.sync.aligned.m16n8k16.row.col.f32.f16.f16.f32 "
        "{%0,%1,%2,%3}, {%4,%5,%6,%7}, {%8,%9}, {%0,%1,%2,%3};"
        : "+f"(d[0]), "+f"(d[1]), "+f"(d[2]), "+f"(d[3])
        : "r"(a[0]), "r"(a[1]), "r"(a[2]), "r"(a[3]), "r"(b0), "r"(b1));
}

__device__ __forceinline__ void unp8(const uint4& u, float* f) {
    const __half2* hp = (const __half2*)&u;
    float2 a = __half22float2(hp[0]), b = __half22float2(hp[1]);
    float2 c = __half22float2(hp[2]), d = __half22float2(hp[3]);
    f[0] = a.x; f[1] = a.y; f[2] = b.x; f[3] = b.y;
    f[4] = c.x; f[5] = c.y; f[6] = d.x; f[7] = d.y;
}

// fast tanh: (e^2x - 1)/(e^2x + 1), clamped; rel err ~1e-6
__device__ __forceinline__ float ftanh(float x) {
    x = fminf(fmaxf(x, -15.f), 15.f);
    float e = __expf(2.f * x);
    return __fdividef(e - 1.f, e + 1.f);
}

// ---------------- fused setup kernels -----------------------------------------
__global__ void k_cvtW(const float* __restrict__ Ws, const float* __restrict__ Wd,
                       const float* __restrict__ bs, const float* __restrict__ bd) {
    int idx = blockIdx.x * blockDim.x + threadIdx.x;
    if (idx <= NN) g_rowoff[idx] = 0;
    if (idx < BG * 64) g_hg[idx] = 0.f;
    if (idx >= 512 * 64) return;
    int n = idx >> 6, k = idx & 63;
    float wt = (n < 256) ? Ws[k * 256 + n] : Wd[k * 256 + (n - 256)];
    float wb = (n < 256) ? Ws[(k + 64) * 256 + n] : Wd[(k + 64) * 256 + (n - 256)];
    g_Wt[idx] = __float2half(wt);
    g_Wb[idx] = __float2half(wb);
    g_Wc[idx] = __float2half(wt + wb);
    if (idx < 512) g_bias2[idx] = (idx < 256) ? bs[idx] : bd[idx - 256];
}

// h0 tiles (fp16) + degree histogram
__global__ void k_h0(const float* __restrict__ feat, const float* __restrict__ W_in,
                     const float* __restrict__ b_in, const int* __restrict__ dst) {
    int idx = blockIdx.x * blockDim.x + threadIdx.x;
    if (idx >= NN * 64) return;
    if (idx < EE) atomicAdd(&g_rowoff[dst[idx] + 1], 1);
    int i = idx >> 6, d = idx & 63;
    const float4* f4 = (const float4*)(feat + i * 16);
    float4 f0 = f4[0], f1 = f4[1], f2 = f4[2], f3 = f4[3];
    float s = b_in[d];
    s = fmaf(f0.x, W_in[0 * 64 + d], s);  s = fmaf(f0.y, W_in[1 * 64 + d], s);
    s = fmaf(f0.z, W_in[2 * 64 + d], s);  s = fmaf(f0.w, W_in[3 * 64 + d], s);
    s = fmaf(f1.x, W_in[4 * 64 + d], s);  s = fmaf(f1.y, W_in[5 * 64 + d], s);
    s = fmaf(f1.z, W_in[6 * 64 + d], s);  s = fmaf(f1.w, W_in[7 * 64 + d], s);
    s = fmaf(f2.x, W_in[8 * 64 + d], s);  s = fmaf(f2.y, W_in[9 * 64 + d], s);
    s = fmaf(f2.z, W_in[10 * 64 + d], s); s = fmaf(f2.w, W_in[11 * 64 + d], s);
    s = fmaf(f3.x, W_in[12 * 64 + d], s); s = fmaf(f3.y, W_in[13 * 64 + d], s);
    s = fmaf(f3.z, W_in[14 * 64 + d], s); s = fmaf(f3.w, W_in[15 * 64 + d], s);
    g_A0h[idx] = __float2half(s);
}

// ---------------- parallel CSR scan -------------------------------------------
__global__ void k_scan1() {
    __shared__ int ws[8];
    int b = blockIdx.x, t = threadIdx.x;
    int lane = t & 31, w = t >> 5;
    int idx = b * 256 + t;
    int x = (idx <= NN) ? g_rowoff[idx] : 0;
#pragma unroll
    for (int off = 1; off < 32; off <<= 1) {
        int y = __shfl_up_sync(0xffffffffu, x, off);
        if (lane >= off) x += y;
    }
    if (lane == 31) ws[w] = x;
    __syncthreads();
    if (w == 0 && lane < 8) {
        int v = ws[lane];
#pragma unroll
        for (int off = 1; off < 8; off <<= 1) {
            int y = __shfl_up_sync(0x000000ffu, v, off, 8);
            if (lane >= off) v += y;
        }
        ws[lane] = v;
    }
    __syncthreads();
    int add = w ? ws[w - 1] : 0;
    x += add;
    if (idx <= NN) g_rowoff[idx] = x;
    if (t == 255) g_bsum[b] = x;
}

__global__ void k_scan3() {
    __shared__ int ws[8];
    int b = blockIdx.x, t = threadIdx.x;
    int lane = t & 31, w = t >> 5;
    int v = (t < b && t < NBLK) ? g_bsum[t] : 0;
#pragma unroll
    for (int off = 16; off > 0; off >>= 1)
        v += __shfl_xor_sync(0xffffffffu, v, off);
    if (lane == 0) ws[w] = v;
    __syncthreads();
    if (t == 0) {
        int s = 0;
#pragma unroll
        for (int i = 0; i < 8; i++) s += ws[i];
        ws[0] = s;
    }
    __syncthreads();
    int add = ws[0];
    int idx = b * 256 + t;
    if (idx <= NN) {
        int r = g_rowoff[idx] + add;
        g_rowoff[idx] = r;
        if (idx < NN) g_cursor[idx] = r;
    }
}

__global__ void k_scatter(const int* __restrict__ src, const int* __restrict__ dst) {
    int e = blockIdx.x * blockDim.x + threadIdx.x;
    if (e < EE) {
        int d = dst[e];
        int p = atomicAdd(&g_cursor[d], 1);
        g_esrc[p] = src[e];
    }
}

// ---------------- fp16 HMMA GEMM ------------------------------------------------
// grid (4, nrb): blockIdx.y = 128-row block; blockIdx.x = q (global cols q*128..+128,
// processed as two 64-col blocks). q<2 -> g_fsh, q>=2 -> g_fdh.
// Warp tile 32x32 (8 warps = 4M x 2N over 128x64). 3 CTAs/SM.
// mode 0 (layer 0):   fsd = A0 @ Wc + bias          (1 segment)
// mode 1 (layers1-3): fsd = A @ Wt + A0 @ Wb + bias (2 segments)
__device__ __forceinline__ void do_seg(uint32_t aBase, uint32_t bBase,
                                       float (&acc)[2][4][4],
                                       int wm, int wn, int a_lrow, int a_c8,
                                       int b_lrow, int b_c8) {
#pragma unroll
    for (int k16 = 0; k16 < 4; k16++) {
        int kc8 = k16 * 2;
        uint32_t af[2][4];
#pragma unroll
        for (int mt = 0; mt < 2; mt++) {
            int r = wm + mt * 16 + a_lrow;
            ldsm_x4(af[mt][0], af[mt][1], af[mt][2], af[mt][3],
                    aBase + SWZ(r, kc8 + a_c8));
        }
        uint32_t bf[2][4];
#pragma unroll
        for (int p = 0; p < 2; p++) {
            int r = wn + p * 16 + b_lrow;
            ldsm_x4(bf[p][0], bf[p][1], bf[p][2], bf[p][3],
                    bBase + SWZ(r, kc8 + b_c8));
        }
#pragma unroll
        for (int mt = 0; mt < 2; mt++)
#pragma unroll
            for (int nt = 0; nt < 4; nt++)
                mma16816h(acc[mt][nt], af[mt],
                          bf[nt >> 1][(nt & 1) * 2], bf[nt >> 1][(nt & 1) * 2 + 1]);
    }
}

__global__ void __launch_bounds__(256, 3) k_mma(int mode) {
    extern __shared__ char sm[];
    const int tid = threadIdx.x;
    const int lane = tid & 31;
    const int wid = tid >> 5;
    const int wm = (wid >> 1) * 32;
    const int wn = (wid & 1) * 32;
    const int row0 = blockIdx.y * 128;
    const int q = blockIdx.x;             // 0..3

    const uint32_t uA = s2u(sm);
    const uint32_t uB = uA + SMEM_A;

    const __half* asrc[2];
    const __half* bsrc[2];
    int nt_;
    if (mode) { asrc[0] = g_Ah;  asrc[1] = g_A0h; bsrc[0] = g_Wt; bsrc[1] = g_Wb; nt_ = 2; }
    else      { asrc[0] = g_A0h;                  bsrc[0] = g_Wc;                 nt_ = 1; }

    // stage A tiles (once): 128 rows x 64 halves each
    for (int a = 0; a < nt_; a++) {
        const __half* s = asrc[a];
        uint32_t base = uA + a * ATILEA;
#pragma unroll
        for (int it = 0; it < 4; it++) {
            int idx = tid + 256 * it;      // 0..1023
            int r = idx >> 3, c8 = idx & 7;
            int grow = row0 + r;
            if (grow < NN)
                cpa16(base + SWZ(r, c8), s + (size_t)grow * 64 + c8 * 8);
            else
                *(float4*)(sm + a * ATILEA + SWZ(r, c8)) = make_float4(0.f, 0.f, 0.f, 0.f);
        }
    }
    // stage B for first 64-col block: rows q*128 .. +64
    for (int b = 0; b < nt_; b++) {
        const __half* s = bsrc[b] + (size_t)(q * 128) * 64;
        uint32_t base = uB + b * BTILE;
#pragma unroll
        for (int it = 0; it < 2; it++) {
            int idx = tid + 256 * it;      // 0..511
            int r = idx >> 3, c8 = idx & 7;
            cpa16(base + SWZ(r, c8), s + (size_t)r * 64 + c8 * 8);
        }
    }
    CPA_COMMIT();
    CPA_WAIT0();
    __syncthreads();

    const int a_lrow = lane & 15;
    const int a_c8 = lane >> 4;
    const int b_lrow = (lane & 7) + ((lane >> 4) << 3);
    const int b_c8 = (lane & 8) >> 3;

    __half* Cb = (q < 2) ? g_fsh : g_fdh;
    const int cbq = (q & 1) * 128;

#pragma unroll
    for (int blk = 0; blk < 2; blk++) {
        const uint32_t bBuf = uB + (blk & 1) * SMEM_Bb;

        if (blk < 1) {
            uint32_t nBuf = uB + SMEM_Bb;
            int nrow0 = q * 128 + 64;
            for (int b = 0; b < nt_; b++) {
                const __half* s = bsrc[b] + (size_t)nrow0 * 64;
                uint32_t base = nBuf + b * BTILE;
#pragma unroll
                for (int it = 0; it < 2; it++) {
                    int idx = tid + 256 * it;
                    int r = idx >> 3, c8 = idx & 7;
                    cpa16(base + SWZ(r, c8), s + (size_t)r * 64 + c8 * 8);
                }
            }
            CPA_COMMIT();
        }

        float acc[2][4][4];
#pragma unroll
        for (int mt = 0; mt < 2; mt++)
#pragma unroll
            for (int nt = 0; nt < 4; nt++)
#pragma unroll
                for (int j = 0; j < 4; j++) acc[mt][nt][j] = 0.f;

        do_seg(uA, bBuf, acc, wm, wn, a_lrow, a_c8, b_lrow, b_c8);
        if (mode)
            do_seg(uA + ATILEA, bBuf + BTILE, acc, wm, wn, a_lrow, a_c8, b_lrow, b_c8);

        // ---- epilogue: + bias, convert fp16, write ----
        {
            int gcol0 = q * 128 + blk * 64;
            int cc0 = cbq + blk * 64;
#pragma unroll
            for (int nt = 0; nt < 4; nt++) {
                int gcol = gcol0 + wn + nt * 8 + (lane & 3) * 2;
                float b0 = g_bias2[gcol], b1 = g_bias2[gcol + 1];
                int cc = cc0 + wn + nt * 8 + (lane & 3) * 2;
#pragma unroll
                for (int mt = 0; mt < 2; mt++) {
                    int rr = row0 + wm + mt * 16 + (lane >> 2);
                    if (rr < NN)
                        *(__half2*)&Cb[(size_t)rr * HD + cc] =
                            __floats2half2_rn(acc[mt][nt][0] + b0, acc[mt][nt][1] + b1);
                    if (rr + 8 < NN)
                        *(__half2*)&Cb[(size_t)(rr + 8) * HD + cc] =
                            __floats2half2_rn(acc[mt][nt][2] + b0, acc[mt][nt][3] + b1);
                }
            }
        }

        if (blk < 1) {
            CPA_WAIT0();
            __syncthreads();
        }
    }
}

// ---------------- edge aggregation: one warp per node -------------------------
// Lane-coalesced index preload (32 edges per chunk), 4-edge batches, fast tanh.
__global__ void __launch_bounds__(256) k_agg(const float* __restrict__ attn, int last) {
    int gw = (blockIdx.x * blockDim.x + threadIdx.x) >> 5;
    int lane = threadIdx.x & 31;
    if (gw >= NN) return;

    int base = lane * 8;
    float fd[8], at[8];
    {
        uint4 u = *(const uint4*)(g_fdh + (size_t)gw * HD + base);
        unp8(u, fd);
        float4 atA = *(const float4*)(attn + base);
        float4 atB = *(const float4*)(attn + base + 4);
        at[0] = atA.x; at[1] = atA.y; at[2] = atA.z; at[3] = atA.w;
        at[4] = atB.x; at[5] = atB.y; at[6] = atB.z; at[7] = atB.w;
    }

    float m = -1e30f, denom = 0.f;
    float acc[8];
#pragma unroll
    for (int j = 0; j < 8; j++) acc[j] = 0.f;

    int e0 = g_rowoff[gw], e1 = g_rowoff[gw + 1];
    const __half* fsb = g_fsh;

    for (int cb = e0; cb < e1; cb += 32) {
        int cnt = min(32, e1 - cb);
        int myi = (lane < cnt) ? g_esrc[cb + lane] : 0;   // coalesced

        for (int i = 0; i < cnt; i += 4) {
            int n = cnt - i;
            int s0 = __shfl_sync(0xffffffffu, myi, i);
            int s1 = __shfl_sync(0xffffffffu, myi, (n > 1) ? i + 1 : i);
            int s2 = __shfl_sync(0xffffffffu, myi, (n > 2) ? i + 2 : i);
            int s3 = __shfl_sync(0xffffffffu, myi, (n > 3) ? i + 3 : i);
            uint4 u0 = *(const uint4*)(fsb + (size_t)s0 * HD + base);
            uint4 u1 = *(const uint4*)(fsb + (size_t)s1 * HD + base);
            uint4 u2 = *(const uint4*)(fsb + (size_t)s2 * HD + base);
            uint4 u3 = *(const uint4*)(fsb + (size_t)s3 * HD + base);

            float f0[8], f1[8], f2[8], f3[8];
            unp8(u0, f0); unp8(u1, f1); unp8(u2, f2); unp8(u3, f3);

            float p0 = 0.f, p1 = 0.f, p2 = 0.f, p3 = 0.f;
#pragma unroll
            for (int j = 0; j < 8; j++) {
                float v;
                v = f0[j] + fd[j]; v = (v > 0.f) ? v : 0.2f * v; p0 = fmaf(v, at[j], p0);
                v = f1[j] + fd[j]; v = (v > 0.f) ? v : 0.2f * v; p1 = fmaf(v, at[j], p1);
                v = f2[j] + fd[j]; v = (v > 0.f) ? v : 0.2f * v; p2 = fmaf(v, at[j], p2);
                v = f3[j] + fd[j]; v = (v > 0.f) ? v : 0.2f * v; p3 = fmaf(v, at[j], p3);
            }
#pragma unroll
            for (int off = 1; off < 8; off <<= 1) {
                p0 += __shfl_xor_sync(0xffffffffu, p0, off);
                p1 += __shfl_xor_sync(0xffffffffu, p1, off);
                p2 += __shfl_xor_sync(0xffffffffu, p2, off);
                p3 += __shfl_xor_sync(0xffffffffu, p3, off);
            }
            if (n < 2) p1 = -1e30f;
            if (n < 3) p2 = -1e30f;
            if (n < 4) p3 = -1e30f;

            float mb = fmaxf(fmaxf(p0, p1), fmaxf(p2, p3));
            float nm = fmaxf(m, mb);
            float sc = __expf(m - nm);
            float w0 = __expf(p0 - nm);
            float w1 = __expf(p1 - nm);
            float w2 = __expf(p2 - nm);
            float w3 = __expf(p3 - nm);
            m = nm;
            denom = fmaf(denom, sc, (w0 + w1) + (w2 + w3));
#pragma unroll
            for (int j = 0; j < 8; j++) {
                float s = fmaf(w0, f0[j], w1 * f1[j]);
                s = fmaf(w2, f2[j], s);
                s = fmaf(w3, f3[j], s);
                acc[j] = fmaf(acc[j], sc, s);
            }
        }
    }

    float inv = (denom > 0.f) ? __fdividef(1.f, denom) : 0.f;
    float t[8];
#pragma unroll
    for (int j = 0; j < 8; j++) t[j] = ftanh(acc[j] * inv);
#pragma unroll
    for (int j = 0; j < 8; j++) {
        t[j] += __shfl_xor_sync(0xffffffffu, t[j], 8);
        t[j] += __shfl_xor_sync(0xffffffffu, t[j], 16);
    }
    if (lane < 8) {
        size_t ofs = (size_t)gw * 64 + lane * 8;
        if (last) {
            float* hout = g_hfin + ofs;
#pragma unroll
            for (int j = 0; j < 8; j++) hout[j] = t[j];
        } else {
            uint4 w;
            __half2* hp = (__half2*)&w;
            hp[0] = __floats2half2_rn(t[0], t[1]);
            hp[1] = __floats2half2_rn(t[2], t[3]);
            hp[2] = __floats2half2_rn(t[4], t[5]);
            hp[3] = __floats2half2_rn(t[6], t[7]);
            *(uint4*)(g_Ah + ofs) = w;
        }
    }
}

// ---------------- graph pooling + output head --------------------------------
__global__ void k_pool(const float* __restrict__ is_root, const int* __restrict__ gid) {
    __shared__ float sh[BG * 64];
    int t = threadIdx.x;
    for (int x = t; x < BG * 64; x += 256) sh[x] = 0.f;
    __syncthreads();
    for (int idx = blockIdx.x * 256 + t; idx < NN * 64; idx += gridDim.x * 256) {
        int i = idx >> 6, d = idx & 63;
        atomicAdd(&sh[(gid[i] << 6) | d], g_hfin[idx] * is_root[i]);
    }
    __syncthreads();
    for (int x = t; x < BG * 64; x += 256) atomicAdd(&g_hg[x], sh[x]);
}

__global__ void k_out(const float* __restrict__ W_out, const float* __restrict__ b_out,
                      float* __restrict__ out) {
    int t = threadIdx.x;
    if (t >= BG * 32) return;
    int b = t >> 5, j = t & 31;
    float s = b_out[j];
#pragma unroll
    for (int d = 0; d < 64; d++) s = fmaf(g_hg[b * 64 + d], W_out[d * 32 + j], s);
    out[t] = s;
}

// ---------------- launcher ----------------------------------------------------
extern "C" void kernel_launch(void* const* d_in, const int* in_sizes, int n_in,
                              void* d_out, int out_size) {
    const float* feat    = (const float*)d_in[0];
    const float* is_root = (const float*)d_in[1];
    const int*   src     = (const int*)  d_in[2];
    const int*   dst     = (const int*)  d_in[3];
    const int*   gid     = (const int*)  d_in[4];
    const float* W_in    = (const float*)d_in[5];
    const float* b_in    = (const float*)d_in[6];
    const float* W_src   = (const float*)d_in[7];
    const float* b_src   = (const float*)d_in[8];
    const float* W_dst   = (const float*)d_in[9];
    const float* b_dst   = (const float*)d_in[10];
    const float* attn    = (const float*)d_in[11];
    const float* W_out   = (const float*)d_in[12];
    const float* b_out   = (const float*)d_in[13];
    float* out = (float*)d_out;

    cudaFuncSetAttribute(k_mma, cudaFuncAttributeMaxDynamicSharedMemorySize, SMEM_TOT);

    const int nrb = (NN + 127) / 128;   // 391 row blocks
    dim3 mgrid(4, nrb);                 // col quadrants x row blocks (1564 CTAs)

    // indices 0-2: weights (+zero), h0+hist, scan1
    k_cvtW<<<NBLK, 256>>>(W_src, W_dst, b_src, b_dst);
    k_h0<<<(NN * 64 + 255) / 256, 256>>>(feat, W_in, b_in, dst);
    k_scan1<<<NBLK, 256>>>();
    // index 3: layer-0 GEMM (needs only weights + h0) -> profiled by ncu
    k_mma<<<mgrid, 256, SMEM_TOT>>>(0);
    // finish CSR while GEMM result is consumed next
    k_scan3<<<NBLK, 256>>>();
    k_scatter<<<(EE + 255) / 256, 256>>>(src, dst);

    k_agg<<<(NN * 32 + 255) / 256, 256>>>(attn, 0);          // layer 0 agg
    for (int L = 1; L < 4; L++) {
        k_mma<<<mgrid, 256, SMEM_TOT>>>(1);
        k_agg<<<(NN * 32 + 255) / 256, 256>>>(attn, L == 3 ? 1 : 0);
    }

    k_pool<<<200, 256>>>(is_root, gid);
    k_out<<<1, 512>>>(W_out, b_out, out);
}